// round 1
// baseline (speedup 1.0000x reference)
#include <cuda_runtime.h>
#include <cuda_bf16.h>

#define N_NODES 50000
#define N_EDGES 600000
#define N_GRAPHS 64
#define IN_DIM 16
#define HID 128
#define OUT_DIM 256
#define N_LAYERS 3

// ---------------- scratch (device globals: allocation-free) ----------------
__device__ float g_h[N_NODES * HID];      // node features
__device__ float g_magg[N_NODES * HID];   // aggregated edge messages
__device__ float g_coord[N_NODES * 3];    // current coordinates
__device__ float g_cacc[N_NODES * 3];     // coord update accumulator
__device__ float g_deg[N_NODES];          // in-edge count per node (row)
__device__ float g_gsum[N_GRAPHS * HID];  // pooled sums
__device__ float g_gcnt[N_GRAPHS];        // nodes per graph

__device__ __forceinline__ float silu_f(float x) {
    return x / (1.0f + __expf(-x));
}

// ---------------- init: zero deg/gsum/gcnt, copy coords ----------------
__global__ void k_init(const float* __restrict__ coord) {
    int i = blockIdx.x * blockDim.x + threadIdx.x;
    if (i < N_NODES * 3) g_coord[i] = coord[i];
    if (i < N_NODES) g_deg[i] = 0.0f;
    if (i < N_GRAPHS * HID) g_gsum[i] = 0.0f;
    if (i < N_GRAPHS) g_gcnt[i] = 0.0f;
}

// zero magg + cacc (per layer)
__global__ void k_zero_acc() {
    int i = blockIdx.x * blockDim.x + threadIdx.x;
    if (i < N_NODES * HID) g_magg[i] = 0.0f;
    if (i < N_NODES * 3) g_cacc[i] = 0.0f;
}

__global__ void k_deg(const int* __restrict__ ei) {
    int e = blockIdx.x * blockDim.x + threadIdx.x;
    if (e < N_EDGES) atomicAdd(&g_deg[ei[e]], 1.0f);
}

__global__ void k_gcnt(const int* __restrict__ batch) {
    int n = blockIdx.x * blockDim.x + threadIdx.x;
    if (n < N_NODES) atomicAdd(&g_gcnt[batch[n]], 1.0f);
}

// h = x @ emb_in_w + emb_in_b   (one node per block, 128 threads)
__global__ void k_emb_in(const float* __restrict__ x,
                         const float* __restrict__ W,
                         const float* __restrict__ b) {
    __shared__ float sx[IN_DIM];
    int n = blockIdx.x;
    if (threadIdx.x < IN_DIM) sx[threadIdx.x] = x[n * IN_DIM + threadIdx.x];
    __syncthreads();
    int j = threadIdx.x;
    float a = b[j];
#pragma unroll
    for (int k = 0; k < IN_DIM; k++) a += sx[k] * W[k * HID + j];
    g_h[n * HID + j] = a;
}

// ---------------- fused edge megakernel ----------------
// per 128-edge tile:
//   m1 = silu(ef @ W1 + b1)           ef = [h[row] | h[col] | radial | eattr]
//   m2 = silu(m1 @ W2 + b2)           -> atomicAdd into g_magg[row]
//   cw = silu(m2 @ CW1 + cb1) @ CW2   -> atomicAdd diff*cw into g_cacc[row]
#define SMA 132  // sA k-major stride (mult of 4 for float4 reads)
#define SMM 129  // sM k-major stride (odd -> bounded write conflicts)

__global__ void __launch_bounds__(256, 2)
k_edge(const int* __restrict__ ei, const float* __restrict__ eattr,
       const float* __restrict__ W1, const float* __restrict__ b1,
       const float* __restrict__ W2, const float* __restrict__ b2,
       const float* __restrict__ CW1, const float* __restrict__ cb1,
       const float* __restrict__ CW2) {
    extern __shared__ float sm[];
    float* sA = sm;                 // [32][SMA] k-major A chunk
    float* sB = sA + 32 * SMA;      // [32][128] B chunk
    float* sM = sB + 32 * 128;      // [128][SMM] k-major intermediate
    int* sR = (int*)(sM + 128 * SMM);
    int* sC = sR + 128;
    float* sRad = (float*)(sC + 128);
    float* sEa = sRad + 128;
    float* sDiff = sEa + 128;       // [128][3]
    float* sPart = sB;              // reuse for cw reduction

    const int tid = threadIdx.x;
    const int tx = tid & 15, ty = tid >> 4;
    const int r0 = ty * 8, c0 = tx * 8;
    const int e0 = blockIdx.x * 128;

    // prologue: edge meta
    if (tid < 128) {
        int e = e0 + tid;
        int r = 0, c = 0;
        float ea = 0.f, d0 = 0.f, d1 = 0.f, d2 = 0.f;
        if (e < N_EDGES) {
            r = ei[e];
            c = ei[N_EDGES + e];
            ea = eattr[e];
            d0 = g_coord[r * 3 + 0] - g_coord[c * 3 + 0];
            d1 = g_coord[r * 3 + 1] - g_coord[c * 3 + 1];
            d2 = g_coord[r * 3 + 2] - g_coord[c * 3 + 2];
        }
        sR[tid] = r; sC[tid] = c;
        sEa[tid] = ea;
        sRad[tid] = d0 * d0 + d1 * d1 + d2 * d2;
        sDiff[tid * 3 + 0] = d0; sDiff[tid * 3 + 1] = d1; sDiff[tid * 3 + 2] = d2;
    }
    __syncthreads();

    float acc[8][8];
#pragma unroll
    for (int i = 0; i < 8; i++)
#pragma unroll
        for (int j = 0; j < 8; j++) acc[i][j] = 0.f;

    // ---- GEMM1: gathered h[row], h[col] halves ----
#pragma unroll 1
    for (int half = 0; half < 2; half++) {
        const int* nid = half ? sC : sR;
#pragma unroll 1
        for (int kc = 0; kc < 4; kc++) {
#pragma unroll
            for (int it = 0; it < 4; it++) {
                int idx = it * 256 + tid;
                int row = idx & 127, kg = idx >> 7;
                const float4 v = *(const float4*)&g_h[nid[row] * HID + kc * 32 + kg * 4];
                sA[(kg * 4 + 0) * SMA + row] = v.x;
                sA[(kg * 4 + 1) * SMA + row] = v.y;
                sA[(kg * 4 + 2) * SMA + row] = v.z;
                sA[(kg * 4 + 3) * SMA + row] = v.w;
            }
#pragma unroll
            for (int it = 0; it < 4; it++) {
                int idx = it * 256 + tid;
                int k = idx >> 5, c4 = idx & 31;
                *(float4*)&sB[k * 128 + c4 * 4] =
                    *(const float4*)&W1[(half * HID + kc * 32 + k) * HID + c4 * 4];
            }
            __syncthreads();
#pragma unroll 8
            for (int k = 0; k < 32; k++) {
                float4 a0 = *(const float4*)&sA[k * SMA + r0];
                float4 a1 = *(const float4*)&sA[k * SMA + r0 + 4];
                float4 q0 = *(const float4*)&sB[k * 128 + c0];
                float4 q1 = *(const float4*)&sB[k * 128 + c0 + 4];
                float av[8] = {a0.x, a0.y, a0.z, a0.w, a1.x, a1.y, a1.z, a1.w};
                float bv[8] = {q0.x, q0.y, q0.z, q0.w, q1.x, q1.y, q1.z, q1.w};
#pragma unroll
                for (int i = 0; i < 8; i++)
#pragma unroll
                    for (int j = 0; j < 8; j++) acc[i][j] += av[i] * bv[j];
            }
            __syncthreads();
        }
    }
    // rank-1 radial / edge_attr rows + bias + silu -> sM (k-major)
    {
        float wr[8], we[8], bj[8];
#pragma unroll
        for (int j = 0; j < 8; j++) {
            wr[j] = W1[256 * HID + c0 + j];
            we[j] = W1[257 * HID + c0 + j];
            bj[j] = b1[c0 + j];
        }
#pragma unroll
        for (int i = 0; i < 8; i++) {
            float rad = sRad[r0 + i], ea = sEa[r0 + i];
#pragma unroll
            for (int j = 0; j < 8; j++) {
                float v = acc[i][j] + rad * wr[j] + ea * we[j] + bj[j];
                sM[(c0 + j) * SMM + r0 + i] = silu_f(v);
            }
        }
    }
    __syncthreads();

    // ---- GEMM2: m2 = silu(m1 @ W2 + b2) ----
#pragma unroll
    for (int i = 0; i < 8; i++)
#pragma unroll
        for (int j = 0; j < 8; j++) acc[i][j] = 0.f;
#pragma unroll 1
    for (int kc = 0; kc < 4; kc++) {
#pragma unroll
        for (int it = 0; it < 4; it++) {
            int idx = it * 256 + tid;
            int k = idx >> 5, c4 = idx & 31;
            *(float4*)&sB[k * 128 + c4 * 4] =
                *(const float4*)&W2[(kc * 32 + k) * HID + c4 * 4];
        }
        __syncthreads();
#pragma unroll 4
        for (int k = 0; k < 32; k++) {
            const float* aRow = &sM[(kc * 32 + k) * SMM + r0];
            float4 q0 = *(const float4*)&sB[k * 128 + c0];
            float4 q1 = *(const float4*)&sB[k * 128 + c0 + 4];
            float bv[8] = {q0.x, q0.y, q0.z, q0.w, q1.x, q1.y, q1.z, q1.w};
#pragma unroll
            for (int i = 0; i < 8; i++) {
                float a = aRow[i];
#pragma unroll
                for (int j = 0; j < 8; j++) acc[i][j] += a * bv[j];
            }
        }
        __syncthreads();
    }
    // bias + silu; magg atomics; store m2 to sM
    {
        float bj[8];
#pragma unroll
        for (int j = 0; j < 8; j++) bj[j] = b2[c0 + j];
#pragma unroll
        for (int i = 0; i < 8; i++)
#pragma unroll
            for (int j = 0; j < 8; j++) acc[i][j] = silu_f(acc[i][j] + bj[j]);
#pragma unroll
        for (int i = 0; i < 8; i++) {
            if (e0 + r0 + i < N_EDGES) {
                float* dst = &g_magg[sR[r0 + i] * HID + c0];
#pragma unroll
                for (int j = 0; j < 8; j++) atomicAdd(dst + j, acc[i][j]);
            }
        }
#pragma unroll
        for (int i = 0; i < 8; i++)
#pragma unroll
            for (int j = 0; j < 8; j++)
                sM[(c0 + j) * SMM + r0 + i] = acc[i][j];
    }
    __syncthreads();

    // ---- GEMM3: c1 = silu(m2 @ CW1 + cb1), cw = c1 @ CW2 ----
#pragma unroll
    for (int i = 0; i < 8; i++)
#pragma unroll
        for (int j = 0; j < 8; j++) acc[i][j] = 0.f;
#pragma unroll 1
    for (int kc = 0; kc < 4; kc++) {
#pragma unroll
        for (int it = 0; it < 4; it++) {
            int idx = it * 256 + tid;
            int k = idx >> 5, c4 = idx & 31;
            *(float4*)&sB[k * 128 + c4 * 4] =
                *(const float4*)&CW1[(kc * 32 + k) * HID + c4 * 4];
        }
        __syncthreads();
#pragma unroll 4
        for (int k = 0; k < 32; k++) {
            const float* aRow = &sM[(kc * 32 + k) * SMM + r0];
            float4 q0 = *(const float4*)&sB[k * 128 + c0];
            float4 q1 = *(const float4*)&sB[k * 128 + c0 + 4];
            float bv[8] = {q0.x, q0.y, q0.z, q0.w, q1.x, q1.y, q1.z, q1.w};
#pragma unroll
            for (int i = 0; i < 8; i++) {
                float a = aRow[i];
#pragma unroll
                for (int j = 0; j < 8; j++) acc[i][j] += a * bv[j];
            }
        }
        __syncthreads();
    }
    {
        float cwv[8], cb[8];
#pragma unroll
        for (int j = 0; j < 8; j++) {
            cwv[j] = CW2[c0 + j];
            cb[j] = cb1[c0 + j];
        }
#pragma unroll
        for (int i = 0; i < 8; i++) {
            float p = 0.f;
#pragma unroll
            for (int j = 0; j < 8; j++)
                p += silu_f(acc[i][j] + cb[j]) * cwv[j];
            sPart[(r0 + i) * 16 + tx] = p;
        }
    }
    __syncthreads();
    if (tid < 128 && e0 + tid < N_EDGES) {
        float s = 0.f;
#pragma unroll
        for (int t = 0; t < 16; t++) s += sPart[tid * 16 + t];
        int node = sR[tid];
        atomicAdd(&g_cacc[node * 3 + 0], sDiff[tid * 3 + 0] * s);
        atomicAdd(&g_cacc[node * 3 + 1], sDiff[tid * 3 + 1] * s);
        atomicAdd(&g_cacc[node * 3 + 2], sDiff[tid * 3 + 2] * s);
    }
}

// coord += cacc / max(deg,1)
__global__ void k_coord_apply() {
    int n = blockIdx.x * blockDim.x + threadIdx.x;
    if (n < N_NODES) {
        float d = g_deg[n];
        if (d < 1.f) d = 1.f;
        float inv = 1.f / d;
        g_coord[n * 3 + 0] += g_cacc[n * 3 + 0] * inv;
        g_coord[n * 3 + 1] += g_cacc[n * 3 + 1] * inv;
        g_coord[n * 3 + 2] += g_cacc[n * 3 + 2] * inv;
    }
}

// ---------------- fused node megakernel ----------------
// h = h + silu([h | magg] @ W1 + b1) @ W2 + b2
__global__ void __launch_bounds__(256, 2)
k_node(const float* __restrict__ W1, const float* __restrict__ b1,
       const float* __restrict__ W2, const float* __restrict__ b2) {
    extern __shared__ float sm[];
    float* sA = sm;
    float* sB = sA + 32 * SMA;
    float* sM = sB + 32 * 128;

    const int tid = threadIdx.x;
    const int tx = tid & 15, ty = tid >> 4;
    const int r0 = ty * 8, c0 = tx * 8;
    const int n0 = blockIdx.x * 128;

    float acc[8][8];
#pragma unroll
    for (int i = 0; i < 8; i++)
#pragma unroll
        for (int j = 0; j < 8; j++) acc[i][j] = 0.f;

#pragma unroll 1
    for (int half = 0; half < 2; half++) {
#pragma unroll 1
        for (int kc = 0; kc < 4; kc++) {
#pragma unroll
            for (int it = 0; it < 4; it++) {
                int idx = it * 256 + tid;
                int row = idx & 127, kg = idx >> 7;
                int node = n0 + row;
                float4 v = make_float4(0.f, 0.f, 0.f, 0.f);
                if (node < N_NODES) {
                    const float* src = half ? g_magg : g_h;
                    v = *(const float4*)&src[node * HID + kc * 32 + kg * 4];
                }
                sA[(kg * 4 + 0) * SMA + row] = v.x;
                sA[(kg * 4 + 1) * SMA + row] = v.y;
                sA[(kg * 4 + 2) * SMA + row] = v.z;
                sA[(kg * 4 + 3) * SMA + row] = v.w;
            }
#pragma unroll
            for (int it = 0; it < 4; it++) {
                int idx = it * 256 + tid;
                int k = idx >> 5, c4 = idx & 31;
                *(float4*)&sB[k * 128 + c4 * 4] =
                    *(const float4*)&W1[(half * HID + kc * 32 + k) * HID + c4 * 4];
            }
            __syncthreads();
#pragma unroll 8
            for (int k = 0; k < 32; k++) {
                float4 a0 = *(const float4*)&sA[k * SMA + r0];
                float4 a1 = *(const float4*)&sA[k * SMA + r0 + 4];
                float4 q0 = *(const float4*)&sB[k * 128 + c0];
                float4 q1 = *(const float4*)&sB[k * 128 + c0 + 4];
                float av[8] = {a0.x, a0.y, a0.z, a0.w, a1.x, a1.y, a1.z, a1.w};
                float bv[8] = {q0.x, q0.y, q0.z, q0.w, q1.x, q1.y, q1.z, q1.w};
#pragma unroll
                for (int i = 0; i < 8; i++)
#pragma unroll
                    for (int j = 0; j < 8; j++) acc[i][j] += av[i] * bv[j];
            }
            __syncthreads();
        }
    }
    {
        float bj[8];
#pragma unroll
        for (int j = 0; j < 8; j++) bj[j] = b1[c0 + j];
#pragma unroll
        for (int i = 0; i < 8; i++)
#pragma unroll
            for (int j = 0; j < 8; j++)
                sM[(c0 + j) * SMM + r0 + i] = silu_f(acc[i][j] + bj[j]);
    }
    __syncthreads();

#pragma unroll
    for (int i = 0; i < 8; i++)
#pragma unroll
        for (int j = 0; j < 8; j++) acc[i][j] = 0.f;
#pragma unroll 1
    for (int kc = 0; kc < 4; kc++) {
#pragma unroll
        for (int it = 0; it < 4; it++) {
            int idx = it * 256 + tid;
            int k = idx >> 5, c4 = idx & 31;
            *(float4*)&sB[k * 128 + c4 * 4] =
                *(const float4*)&W2[(kc * 32 + k) * HID + c4 * 4];
        }
        __syncthreads();
#pragma unroll 4
        for (int k = 0; k < 32; k++) {
            const float* aRow = &sM[(kc * 32 + k) * SMM + r0];
            float4 q0 = *(const float4*)&sB[k * 128 + c0];
            float4 q1 = *(const float4*)&sB[k * 128 + c0 + 4];
            float bv[8] = {q0.x, q0.y, q0.z, q0.w, q1.x, q1.y, q1.z, q1.w};
#pragma unroll
            for (int i = 0; i < 8; i++) {
                float a = aRow[i];
#pragma unroll
                for (int j = 0; j < 8; j++) acc[i][j] += a * bv[j];
            }
        }
        __syncthreads();
    }
    {
        float bj[8];
#pragma unroll
        for (int j = 0; j < 8; j++) bj[j] = b2[c0 + j];
#pragma unroll
        for (int i = 0; i < 8; i++) {
            int node = n0 + r0 + i;
            if (node < N_NODES) {
#pragma unroll
                for (int j = 0; j < 8; j++) {
                    int off = node * HID + c0 + j;
                    g_h[off] = g_h[off] + acc[i][j] + bj[j];
                }
            }
        }
    }
}

// ---------------- emb_out GEMM + batched mean-pool (batch is sorted) ----------------
__global__ void __launch_bounds__(256, 2)
k_pool(const int* __restrict__ batch,
       const float* __restrict__ W, const float* __restrict__ b) {
    extern __shared__ float sm[];
    float* sA = sm;
    float* sB = sA + 32 * SMA;
    float* sMr = sB + 32 * 128;       // row-major [128][132]
    int* sBat = (int*)(sMr + 128 * 132);

    const int tid = threadIdx.x;
    const int tx = tid & 15, ty = tid >> 4;
    const int r0 = ty * 8, c0 = tx * 8;
    const int n0 = blockIdx.x * 128;

    if (tid < 128)
        sBat[tid] = (n0 + tid < N_NODES) ? batch[n0 + tid] : -1;

    float acc[8][8];
#pragma unroll
    for (int i = 0; i < 8; i++)
#pragma unroll
        for (int j = 0; j < 8; j++) acc[i][j] = 0.f;

#pragma unroll 1
    for (int kc = 0; kc < 4; kc++) {
#pragma unroll
        for (int it = 0; it < 4; it++) {
            int idx = it * 256 + tid;
            int row = idx & 127, kg = idx >> 7;
            int node = n0 + row;
            float4 v = make_float4(0.f, 0.f, 0.f, 0.f);
            if (node < N_NODES)
                v = *(const float4*)&g_h[node * HID + kc * 32 + kg * 4];
            sA[(kg * 4 + 0) * SMA + row] = v.x;
            sA[(kg * 4 + 1) * SMA + row] = v.y;
            sA[(kg * 4 + 2) * SMA + row] = v.z;
            sA[(kg * 4 + 3) * SMA + row] = v.w;
        }
#pragma unroll
        for (int it = 0; it < 4; it++) {
            int idx = it * 256 + tid;
            int k = idx >> 5, c4 = idx & 31;
            *(float4*)&sB[k * 128 + c4 * 4] =
                *(const float4*)&W[(kc * 32 + k) * HID + c4 * 4];
        }
        __syncthreads();
#pragma unroll 8
        for (int k = 0; k < 32; k++) {
            float4 a0 = *(const float4*)&sA[k * SMA + r0];
            float4 a1 = *(const float4*)&sA[k * SMA + r0 + 4];
            float4 q0 = *(const float4*)&sB[k * 128 + c0];
            float4 q1 = *(const float4*)&sB[k * 128 + c0 + 4];
            float av[8] = {a0.x, a0.y, a0.z, a0.w, a1.x, a1.y, a1.z, a1.w};
            float bv[8] = {q0.x, q0.y, q0.z, q0.w, q1.x, q1.y, q1.z, q1.w};
#pragma unroll
            for (int i = 0; i < 8; i++)
#pragma unroll
                for (int j = 0; j < 8; j++) acc[i][j] += av[i] * bv[j];
        }
        __syncthreads();
    }
    {
#pragma unroll
        for (int i = 0; i < 8; i++)
#pragma unroll
            for (int j = 0; j < 8; j++)
                sMr[(r0 + i) * 132 + c0 + j] = acc[i][j] + b[c0 + j];
    }
    __syncthreads();

    // run-length pooled atomics (batch sorted -> few segments per block)
    if (tid < 128) {
        int j = tid;
        int gprev = sBat[0];
        float s = 0.f;
        for (int r = 0; r < 128; r++) {
            int g = sBat[r];
            if (g != gprev) {
                if (gprev >= 0) atomicAdd(&g_gsum[gprev * HID + j], s);
                s = 0.f;
                gprev = g;
            }
            if (g >= 0) s += sMr[r * 132 + j];
        }
        if (gprev >= 0) atomicAdd(&g_gsum[gprev * HID + j], s);
    }
}

// out = (gsum/gcnt) @ fc_w + fc_b     one graph per block
__global__ void k_final(const float* __restrict__ fcw,
                        const float* __restrict__ fcb,
                        float* __restrict__ out) {
    __shared__ float sg[HID];
    int g = blockIdx.x;
    if (threadIdx.x < HID) {
        float cnt = g_gcnt[g];
        if (cnt < 1.f) cnt = 1.f;
        sg[threadIdx.x] = g_gsum[g * HID + threadIdx.x] / cnt;
    }
    __syncthreads();
    int o = threadIdx.x;
    float a = fcb[o];
#pragma unroll 8
    for (int k = 0; k < HID; k++) a += sg[k] * fcw[k * OUT_DIM + o];
    out[g * OUT_DIM + o] = a;
}

// ---------------- host ----------------
extern "C" void kernel_launch(void* const* d_in, const int* in_sizes, int n_in,
                              void* d_out, int out_size) {
    const float* x        = (const float*)d_in[0];
    const int*   ei       = (const int*)d_in[1];
    const float* coord    = (const float*)d_in[2];
    const float* eattr    = (const float*)d_in[3];
    const int*   batch    = (const int*)d_in[4];
    const float* emb_in_w = (const float*)d_in[5];
    const float* emb_in_b = (const float*)d_in[6];
    const float* ew1      = (const float*)d_in[7];
    const float* eb1      = (const float*)d_in[8];
    const float* ew2      = (const float*)d_in[9];
    const float* eb2      = (const float*)d_in[10];
    const float* nw1      = (const float*)d_in[11];
    const float* nb1      = (const float*)d_in[12];
    const float* nw2      = (const float*)d_in[13];
    const float* nb2      = (const float*)d_in[14];
    const float* cw1      = (const float*)d_in[15];
    const float* cb1      = (const float*)d_in[16];
    const float* cw2      = (const float*)d_in[17];
    const float* eow      = (const float*)d_in[18];
    const float* eob      = (const float*)d_in[19];
    const float* fcw      = (const float*)d_in[20];
    const float* fcb      = (const float*)d_in[21];
    float* out = (float*)d_out;

    const int EDGE_SMEM = (32 * SMA + 32 * 128 + 128 * SMM + 256 + 128 + 128 + 384) * 4;
    const int NODE_SMEM = (32 * SMA + 32 * 128 + 128 * SMM) * 4;
    const int POOL_SMEM = (32 * SMA + 32 * 128 + 128 * 132 + 128) * 4;

    cudaFuncSetAttribute(k_edge, cudaFuncAttributeMaxDynamicSharedMemorySize, EDGE_SMEM);
    cudaFuncSetAttribute(k_node, cudaFuncAttributeMaxDynamicSharedMemorySize, NODE_SMEM);
    cudaFuncSetAttribute(k_pool, cudaFuncAttributeMaxDynamicSharedMemorySize, POOL_SMEM);

    const int EB = (N_EDGES + 127) / 128;   // 4688
    const int NB = (N_NODES + 127) / 128;   // 391

    k_init<<<(N_NODES * 3 + 255) / 256, 256>>>(coord);
    k_deg<<<(N_EDGES + 255) / 256, 256>>>(ei);
    k_gcnt<<<(N_NODES + 255) / 256, 256>>>(batch);
    k_emb_in<<<N_NODES, HID>>>(x, emb_in_w, emb_in_b);

    for (int l = 0; l < N_LAYERS; l++) {
        k_zero_acc<<<(N_NODES * HID + 255) / 256, 256>>>();
        k_edge<<<EB, 256, EDGE_SMEM>>>(
            ei, eattr,
            ew1 + l * 258 * HID, eb1 + l * HID,
            ew2 + l * HID * HID, eb2 + l * HID,
            cw1 + l * HID * HID, cb1 + l * HID,
            cw2 + l * HID);
        k_coord_apply<<<(N_NODES + 255) / 256, 256>>>();
        k_node<<<NB, 256, NODE_SMEM>>>(
            nw1 + l * 256 * HID, nb1 + l * HID,
            nw2 + l * HID * HID, nb2 + l * HID);
    }

    k_pool<<<NB, 256, POOL_SMEM>>>(batch, eow, eob);
    k_final<<<N_GRAPHS, OUT_DIM>>>(fcw, fcb, out);
}

// round 4
// speedup vs baseline: 1.1208x; 1.1208x over previous
#include <cuda_runtime.h>
#include <cuda_bf16.h>

#define N_NODES 50000
#define N_EDGES 600000
#define N_GRAPHS 64
#define IN_DIM 16
#define HID 128
#define OUT_DIM 256
#define N_LAYERS 3

typedef unsigned long long ull;

// ---------------- scratch (device globals: allocation-free) ----------------
__device__ float g_h[N_NODES * HID];      // node features
__device__ float g_magg[N_NODES * HID];   // aggregated edge messages
__device__ float g_coord[N_NODES * 3];    // current coordinates
__device__ float g_cacc[N_NODES * 3];     // coord update accumulator
__device__ float g_deg[N_NODES];          // in-edge count per node (row)
__device__ float g_gsum[N_GRAPHS * HID];  // pooled sums
__device__ float g_gcnt[N_GRAPHS];        // nodes per graph

__device__ __forceinline__ float silu_f(float x) {
    return x / (1.0f + __expf(-x));
}

// ---- packed f32x2 helpers (sm_103a FFMA2) ----
__device__ __forceinline__ ull pack_dup(float x) {
    ull r; asm("mov.b64 %0, {%1, %1};" : "=l"(r) : "f"(x)); return r;
}
__device__ __forceinline__ void unpack2(ull v, float& lo, float& hi) {
    asm("mov.b64 {%0, %1}, %2;" : "=f"(lo), "=f"(hi) : "l"(v));
}
__device__ __forceinline__ void ffma2(ull& d, ull a, ull b) {
    asm("fma.rn.f32x2 %0, %1, %2, %0;" : "+l"(d) : "l"(a), "l"(b));
}
__device__ __forceinline__ void red_v4(float* p, float a, float b, float c, float d) {
    asm volatile("red.global.add.v4.f32 [%0], {%1, %2, %3, %4};"
                 :: "l"(p), "f"(a), "f"(b), "f"(c), "f"(d) : "memory");
}

// ---------------- init: zero deg/gsum/gcnt, copy coords ----------------
__global__ void k_init(const float* __restrict__ coord) {
    int i = blockIdx.x * blockDim.x + threadIdx.x;
    if (i < N_NODES * 3) g_coord[i] = coord[i];
    if (i < N_NODES) g_deg[i] = 0.0f;
    if (i < N_GRAPHS * HID) g_gsum[i] = 0.0f;
    if (i < N_GRAPHS) g_gcnt[i] = 0.0f;
}

// zero magg + cacc (per layer)
__global__ void k_zero_acc() {
    int i = blockIdx.x * blockDim.x + threadIdx.x;
    if (i < N_NODES * HID / 4) *(float4*)&g_magg[i * 4] = make_float4(0.f, 0.f, 0.f, 0.f);
    if (i < N_NODES * 3) g_cacc[i] = 0.0f;
}

__global__ void k_deg(const int* __restrict__ ei) {
    int e = blockIdx.x * blockDim.x + threadIdx.x;
    if (e < N_EDGES) atomicAdd(&g_deg[ei[e]], 1.0f);
}

__global__ void k_gcnt(const int* __restrict__ batch) {
    int n = blockIdx.x * blockDim.x + threadIdx.x;
    if (n < N_NODES) atomicAdd(&g_gcnt[batch[n]], 1.0f);
}

// h = x @ emb_in_w + emb_in_b   (one node per block, 128 threads)
__global__ void k_emb_in(const float* __restrict__ x,
                         const float* __restrict__ W,
                         const float* __restrict__ b) {
    __shared__ float sx[IN_DIM];
    int n = blockIdx.x;
    if (threadIdx.x < IN_DIM) sx[threadIdx.x] = x[n * IN_DIM + threadIdx.x];
    __syncthreads();
    int j = threadIdx.x;
    float a = b[j];
#pragma unroll
    for (int k = 0; k < IN_DIM; k++) a += sx[k] * W[k * HID + j];
    g_h[n * HID + j] = a;
}

#define SMA 132  // sA k-major stride (even -> LDS.64 pairs; mult of 4 for float4)
#define SMM 129  // sM k-major stride (odd -> bounded write conflicts)

// microkernel A: pack along i (A pairs via LDS.64 from sA; B dup'd)
#define MK_PACKI(ACC2)                                                          \
    {                                                                           \
        const ull* ap = (const ull*)&sA[k * SMA + r0];                          \
        ull a01 = ap[0], a23 = ap[1], a45 = ap[2], a67 = ap[3];                 \
        float4 q0 = *(const float4*)&sB[k * 128 + c0];                          \
        float4 q1 = *(const float4*)&sB[k * 128 + c0 + 4];                      \
        ull bd0 = pack_dup(q0.x), bd1 = pack_dup(q0.y);                         \
        ull bd2 = pack_dup(q0.z), bd3 = pack_dup(q0.w);                         \
        ull bd4 = pack_dup(q1.x), bd5 = pack_dup(q1.y);                         \
        ull bd6 = pack_dup(q1.z), bd7 = pack_dup(q1.w);                         \
        ffma2(ACC2[0][0], a01, bd0); ffma2(ACC2[0][1], a01, bd1);               \
        ffma2(ACC2[0][2], a01, bd2); ffma2(ACC2[0][3], a01, bd3);               \
        ffma2(ACC2[0][4], a01, bd4); ffma2(ACC2[0][5], a01, bd5);               \
        ffma2(ACC2[0][6], a01, bd6); ffma2(ACC2[0][7], a01, bd7);               \
        ffma2(ACC2[1][0], a23, bd0); ffma2(ACC2[1][1], a23, bd1);               \
        ffma2(ACC2[1][2], a23, bd2); ffma2(ACC2[1][3], a23, bd3);               \
        ffma2(ACC2[1][4], a23, bd4); ffma2(ACC2[1][5], a23, bd5);               \
        ffma2(ACC2[1][6], a23, bd6); ffma2(ACC2[1][7], a23, bd7);               \
        ffma2(ACC2[2][0], a45, bd0); ffma2(ACC2[2][1], a45, bd1);               \
        ffma2(ACC2[2][2], a45, bd2); ffma2(ACC2[2][3], a45, bd3);               \
        ffma2(ACC2[2][4], a45, bd4); ffma2(ACC2[2][5], a45, bd5);               \
        ffma2(ACC2[2][6], a45, bd6); ffma2(ACC2[2][7], a45, bd7);               \
        ffma2(ACC2[3][0], a67, bd0); ffma2(ACC2[3][1], a67, bd1);               \
        ffma2(ACC2[3][2], a67, bd2); ffma2(ACC2[3][3], a67, bd3);               \
        ffma2(ACC2[3][4], a67, bd4); ffma2(ACC2[3][5], a67, bd5);               \
        ffma2(ACC2[3][6], a67, bd6); ffma2(ACC2[3][7], a67, bd7);               \
    }

// microkernel B: pack along j (B pairs via LDS.64 from sB; A dup'd from sM)
#define MK_PACKJ(ACC2, KIDX)                                                    \
    {                                                                           \
        const float* aRow = &sM[(KIDX) * SMM + r0];                             \
        const ull* bp = (const ull*)&sB[k * 128 + c0];                          \
        ull b0 = bp[0], b1 = bp[1], b2 = bp[2], b3 = bp[3];                     \
        _Pragma("unroll")                                                       \
        for (int i = 0; i < 8; i++) {                                           \
            ull ad = pack_dup(aRow[i]);                                         \
            ffma2(ACC2[i][0], ad, b0); ffma2(ACC2[i][1], ad, b1);               \
            ffma2(ACC2[i][2], ad, b2); ffma2(ACC2[i][3], ad, b3);               \
        }                                                                       \
    }

// ---------------- fused edge megakernel ----------------
__global__ void __launch_bounds__(256, 2)
k_edge(const int* __restrict__ ei, const float* __restrict__ eattr,
       const float* __restrict__ W1, const float* __restrict__ b1,
       const float* __restrict__ W2, const float* __restrict__ b2,
       const float* __restrict__ CW1, const float* __restrict__ cb1,
       const float* __restrict__ CW2) {
    extern __shared__ float sm[];
    float* sA = sm;                 // [32][SMA] k-major A chunk
    float* sB = sA + 32 * SMA;      // [32][128] B chunk
    float* sM = sB + 32 * 128;      // [128][SMM] k-major intermediate
    int* sR = (int*)(sM + 128 * SMM);
    int* sC = sR + 128;
    float* sRad = (float*)(sC + 128);
    float* sEa = sRad + 128;
    float* sDiff = sEa + 128;       // [128][3]
    float* sPart = sB;              // reuse for cw reduction

    const int tid = threadIdx.x;
    const int tx = tid & 15, ty = tid >> 4;
    const int r0 = ty * 8, c0 = tx * 8;
    const int e0 = blockIdx.x * 128;

    // prologue: edge meta
    if (tid < 128) {
        int e = e0 + tid;
        int r = 0, c = 0;
        float ea = 0.f, d0 = 0.f, d1 = 0.f, d2 = 0.f;
        if (e < N_EDGES) {
            r = ei[e];
            c = ei[N_EDGES + e];
            ea = eattr[e];
            d0 = g_coord[r * 3 + 0] - g_coord[c * 3 + 0];
            d1 = g_coord[r * 3 + 1] - g_coord[c * 3 + 1];
            d2 = g_coord[r * 3 + 2] - g_coord[c * 3 + 2];
        }
        sR[tid] = r; sC[tid] = c;
        sEa[tid] = ea;
        sRad[tid] = d0 * d0 + d1 * d1 + d2 * d2;
        sDiff[tid * 3 + 0] = d0; sDiff[tid * 3 + 1] = d1; sDiff[tid * 3 + 2] = d2;
    }
    __syncthreads();

    ull acc2[4][8];
#pragma unroll
    for (int i = 0; i < 4; i++)
#pragma unroll
        for (int j = 0; j < 8; j++) acc2[i][j] = 0ull;

    // ---- GEMM1: gathered h[row], h[col] halves (pack along i) ----
#pragma unroll 1
    for (int half = 0; half < 2; half++) {
        const int* nid = half ? sC : sR;
#pragma unroll 1
        for (int kc = 0; kc < 4; kc++) {
#pragma unroll
            for (int it = 0; it < 4; it++) {
                int idx = it * 256 + tid;
                int row = idx & 127, kg = idx >> 7;
                const float4 v = *(const float4*)&g_h[nid[row] * HID + kc * 32 + kg * 4];
                sA[(kg * 4 + 0) * SMA + row] = v.x;
                sA[(kg * 4 + 1) * SMA + row] = v.y;
                sA[(kg * 4 + 2) * SMA + row] = v.z;
                sA[(kg * 4 + 3) * SMA + row] = v.w;
            }
#pragma unroll
            for (int it = 0; it < 4; it++) {
                int idx = it * 256 + tid;
                int k = idx >> 5, c4 = idx & 31;
                *(float4*)&sB[k * 128 + c4 * 4] =
                    *(const float4*)&W1[(half * HID + kc * 32 + k) * HID + c4 * 4];
            }
            __syncthreads();
#pragma unroll 8
            for (int k = 0; k < 32; k++) MK_PACKI(acc2)
            __syncthreads();
        }
    }
    // unpack + rank-1 radial / edge_attr rows + bias + silu -> sM (k-major)
    {
        float acc[8][8];
#pragma unroll
        for (int i2 = 0; i2 < 4; i2++)
#pragma unroll
            for (int j = 0; j < 8; j++)
                unpack2(acc2[i2][j], acc[2 * i2][j], acc[2 * i2 + 1][j]);
        float wr[8], we[8], bj[8];
#pragma unroll
        for (int j = 0; j < 8; j++) {
            wr[j] = W1[256 * HID + c0 + j];
            we[j] = W1[257 * HID + c0 + j];
            bj[j] = b1[c0 + j];
        }
#pragma unroll
        for (int i = 0; i < 8; i++) {
            float rad = sRad[r0 + i], ea = sEa[r0 + i];
#pragma unroll
            for (int j = 0; j < 8; j++) {
                float v = acc[i][j] + rad * wr[j] + ea * we[j] + bj[j];
                sM[(c0 + j) * SMM + r0 + i] = silu_f(v);
            }
        }
    }
    __syncthreads();

    // ---- GEMM2: m2 = silu(m1 @ W2 + b2)  (pack along j) ----
    ull acc2b[8][4];
#pragma unroll
    for (int i = 0; i < 8; i++)
#pragma unroll
        for (int j = 0; j < 4; j++) acc2b[i][j] = 0ull;
#pragma unroll 1
    for (int kc = 0; kc < 4; kc++) {
#pragma unroll
        for (int it = 0; it < 4; it++) {
            int idx = it * 256 + tid;
            int k = idx >> 5, c4 = idx & 31;
            *(float4*)&sB[k * 128 + c4 * 4] =
                *(const float4*)&W2[(kc * 32 + k) * HID + c4 * 4];
        }
        __syncthreads();
#pragma unroll 4
        for (int k = 0; k < 32; k++) MK_PACKJ(acc2b, kc * 32 + k)
        __syncthreads();
    }
    // bias + silu; magg vector-red; store m2 to sM
    {
        float acc[8][8];
#pragma unroll
        for (int i = 0; i < 8; i++)
#pragma unroll
            for (int j2 = 0; j2 < 4; j2++)
                unpack2(acc2b[i][j2], acc[i][2 * j2], acc[i][2 * j2 + 1]);
        float bj[8];
#pragma unroll
        for (int j = 0; j < 8; j++) bj[j] = b2[c0 + j];
#pragma unroll
        for (int i = 0; i < 8; i++)
#pragma unroll
            for (int j = 0; j < 8; j++) acc[i][j] = silu_f(acc[i][j] + bj[j]);
#pragma unroll
        for (int i = 0; i < 8; i++) {
            if (e0 + r0 + i < N_EDGES) {
                float* dst = &g_magg[sR[r0 + i] * HID + c0];
                red_v4(dst, acc[i][0], acc[i][1], acc[i][2], acc[i][3]);
                red_v4(dst + 4, acc[i][4], acc[i][5], acc[i][6], acc[i][7]);
            }
        }
#pragma unroll
        for (int i = 0; i < 8; i++)
#pragma unroll
            for (int j = 0; j < 8; j++)
                sM[(c0 + j) * SMM + r0 + i] = acc[i][j];
    }
    __syncthreads();

    // ---- GEMM3: c1 = silu(m2 @ CW1 + cb1), cw = c1 @ CW2  (pack along j) ----
#pragma unroll
    for (int i = 0; i < 8; i++)
#pragma unroll
        for (int j = 0; j < 4; j++) acc2b[i][j] = 0ull;
#pragma unroll 1
    for (int kc = 0; kc < 4; kc++) {
#pragma unroll
        for (int it = 0; it < 4; it++) {
            int idx = it * 256 + tid;
            int k = idx >> 5, c4 = idx & 31;
            *(float4*)&sB[k * 128 + c4 * 4] =
                *(const float4*)&CW1[(kc * 32 + k) * HID + c4 * 4];
        }
        __syncthreads();
#pragma unroll 4
        for (int k = 0; k < 32; k++) MK_PACKJ(acc2b, kc * 32 + k)
        __syncthreads();
    }
    {
        float acc[8][8];
#pragma unroll
        for (int i = 0; i < 8; i++)
#pragma unroll
            for (int j2 = 0; j2 < 4; j2++)
                unpack2(acc2b[i][j2], acc[i][2 * j2], acc[i][2 * j2 + 1]);
        float cwv[8], cb[8];
#pragma unroll
        for (int j = 0; j < 8; j++) {
            cwv[j] = CW2[c0 + j];
            cb[j] = cb1[c0 + j];
        }
#pragma unroll
        for (int i = 0; i < 8; i++) {
            float p = 0.f;
#pragma unroll
            for (int j = 0; j < 8; j++)
                p += silu_f(acc[i][j] + cb[j]) * cwv[j];
            sPart[(r0 + i) * 16 + tx] = p;
        }
    }
    __syncthreads();
    if (tid < 128 && e0 + tid < N_EDGES) {
        float s = 0.f;
#pragma unroll
        for (int t = 0; t < 16; t++) s += sPart[tid * 16 + t];
        int node = sR[tid];
        atomicAdd(&g_cacc[node * 3 + 0], sDiff[tid * 3 + 0] * s);
        atomicAdd(&g_cacc[node * 3 + 1], sDiff[tid * 3 + 1] * s);
        atomicAdd(&g_cacc[node * 3 + 2], sDiff[tid * 3 + 2] * s);
    }
}

// coord += cacc / max(deg,1)
__global__ void k_coord_apply() {
    int n = blockIdx.x * blockDim.x + threadIdx.x;
    if (n < N_NODES) {
        float d = g_deg[n];
        if (d < 1.f) d = 1.f;
        float inv = 1.f / d;
        g_coord[n * 3 + 0] += g_cacc[n * 3 + 0] * inv;
        g_coord[n * 3 + 1] += g_cacc[n * 3 + 1] * inv;
        g_coord[n * 3 + 2] += g_cacc[n * 3 + 2] * inv;
    }
}

// ---------------- fused node megakernel ----------------
// h = h + silu([h | magg] @ W1 + b1) @ W2 + b2
__global__ void __launch_bounds__(256, 2)
k_node(const float* __restrict__ W1, const float* __restrict__ b1,
       const float* __restrict__ W2, const float* __restrict__ b2) {
    extern __shared__ float sm[];
    float* sA = sm;
    float* sB = sA + 32 * SMA;
    float* sM = sB + 32 * 128;

    const int tid = threadIdx.x;
    const int tx = tid & 15, ty = tid >> 4;
    const int r0 = ty * 8, c0 = tx * 8;
    const int n0 = blockIdx.x * 128;

    ull acc2[4][8];
#pragma unroll
    for (int i = 0; i < 4; i++)
#pragma unroll
        for (int j = 0; j < 8; j++) acc2[i][j] = 0ull;

#pragma unroll 1
    for (int half = 0; half < 2; half++) {
#pragma unroll 1
        for (int kc = 0; kc < 4; kc++) {
#pragma unroll
            for (int it = 0; it < 4; it++) {
                int idx = it * 256 + tid;
                int row = idx & 127, kg = idx >> 7;
                int node = n0 + row;
                float4 v = make_float4(0.f, 0.f, 0.f, 0.f);
                if (node < N_NODES) {
                    const float* src = half ? g_magg : g_h;
                    v = *(const float4*)&src[node * HID + kc * 32 + kg * 4];
                }
                sA[(kg * 4 + 0) * SMA + row] = v.x;
                sA[(kg * 4 + 1) * SMA + row] = v.y;
                sA[(kg * 4 + 2) * SMA + row] = v.z;
                sA[(kg * 4 + 3) * SMA + row] = v.w;
            }
#pragma unroll
            for (int it = 0; it < 4; it++) {
                int idx = it * 256 + tid;
                int k = idx >> 5, c4 = idx & 31;
                *(float4*)&sB[k * 128 + c4 * 4] =
                    *(const float4*)&W1[(half * HID + kc * 32 + k) * HID + c4 * 4];
            }
            __syncthreads();
#pragma unroll 8
            for (int k = 0; k < 32; k++) MK_PACKI(acc2)
            __syncthreads();
        }
    }
    {
        float acc[8][8];
#pragma unroll
        for (int i2 = 0; i2 < 4; i2++)
#pragma unroll
            for (int j = 0; j < 8; j++)
                unpack2(acc2[i2][j], acc[2 * i2][j], acc[2 * i2 + 1][j]);
        float bj[8];
#pragma unroll
        for (int j = 0; j < 8; j++) bj[j] = b1[c0 + j];
#pragma unroll
        for (int i = 0; i < 8; i++)
#pragma unroll
            for (int j = 0; j < 8; j++)
                sM[(c0 + j) * SMM + r0 + i] = silu_f(acc[i][j] + bj[j]);
    }
    __syncthreads();

    ull acc2b[8][4];
#pragma unroll
    for (int i = 0; i < 8; i++)
#pragma unroll
        for (int j = 0; j < 4; j++) acc2b[i][j] = 0ull;
#pragma unroll 1
    for (int kc = 0; kc < 4; kc++) {
#pragma unroll
        for (int it = 0; it < 4; it++) {
            int idx = it * 256 + tid;
            int k = idx >> 5, c4 = idx & 31;
            *(float4*)&sB[k * 128 + c4 * 4] =
                *(const float4*)&W2[(kc * 32 + k) * HID + c4 * 4];
        }
        __syncthreads();
#pragma unroll 4
        for (int k = 0; k < 32; k++) MK_PACKJ(acc2b, kc * 32 + k)
        __syncthreads();
    }
    {
        float acc[8][8];
#pragma unroll
        for (int i = 0; i < 8; i++)
#pragma unroll
            for (int j2 = 0; j2 < 4; j2++)
                unpack2(acc2b[i][j2], acc[i][2 * j2], acc[i][2 * j2 + 1]);
        float bj[8];
#pragma unroll
        for (int j = 0; j < 8; j++) bj[j] = b2[c0 + j];
#pragma unroll
        for (int i = 0; i < 8; i++) {
            int node = n0 + r0 + i;
            if (node < N_NODES) {
                float4 h0 = *(float4*)&g_h[node * HID + c0];
                float4 h1 = *(float4*)&g_h[node * HID + c0 + 4];
                h0.x += acc[i][0] + bj[0]; h0.y += acc[i][1] + bj[1];
                h0.z += acc[i][2] + bj[2]; h0.w += acc[i][3] + bj[3];
                h1.x += acc[i][4] + bj[4]; h1.y += acc[i][5] + bj[5];
                h1.z += acc[i][6] + bj[6]; h1.w += acc[i][7] + bj[7];
                *(float4*)&g_h[node * HID + c0] = h0;
                *(float4*)&g_h[node * HID + c0 + 4] = h1;
            }
        }
    }
}

// ---------------- emb_out GEMM + batched mean-pool (batch is sorted) ----------------
__global__ void __launch_bounds__(256, 2)
k_pool(const int* __restrict__ batch,
       const float* __restrict__ W, const float* __restrict__ b) {
    extern __shared__ float sm[];
    float* sA = sm;
    float* sB = sA + 32 * SMA;
    float* sMr = sB + 32 * 128;       // row-major [128][132]
    int* sBat = (int*)(sMr + 128 * 132);

    const int tid = threadIdx.x;
    const int tx = tid & 15, ty = tid >> 4;
    const int r0 = ty * 8, c0 = tx * 8;
    const int n0 = blockIdx.x * 128;

    if (tid < 128)
        sBat[tid] = (n0 + tid < N_NODES) ? batch[n0 + tid] : -1;

    ull acc2[4][8];
#pragma unroll
    for (int i = 0; i < 4; i++)
#pragma unroll
        for (int j = 0; j < 8; j++) acc2[i][j] = 0ull;

#pragma unroll 1
    for (int kc = 0; kc < 4; kc++) {
#pragma unroll
        for (int it = 0; it < 4; it++) {
            int idx = it * 256 + tid;
            int row = idx & 127, kg = idx >> 7;
            int node = n0 + row;
            float4 v = make_float4(0.f, 0.f, 0.f, 0.f);
            if (node < N_NODES)
                v = *(const float4*)&g_h[node * HID + kc * 32 + kg * 4];
            sA[(kg * 4 + 0) * SMA + row] = v.x;
            sA[(kg * 4 + 1) * SMA + row] = v.y;
            sA[(kg * 4 + 2) * SMA + row] = v.z;
            sA[(kg * 4 + 3) * SMA + row] = v.w;
        }
#pragma unroll
        for (int it = 0; it < 4; it++) {
            int idx = it * 256 + tid;
            int k = idx >> 5, c4 = idx & 31;
            *(float4*)&sB[k * 128 + c4 * 4] =
                *(const float4*)&W[(kc * 32 + k) * HID + c4 * 4];
        }
        __syncthreads();
#pragma unroll 8
        for (int k = 0; k < 32; k++) MK_PACKI(acc2)
        __syncthreads();
    }
    {
        float acc[8][8];
#pragma unroll
        for (int i2 = 0; i2 < 4; i2++)
#pragma unroll
            for (int j = 0; j < 8; j++)
                unpack2(acc2[i2][j], acc[2 * i2][j], acc[2 * i2 + 1][j]);
#pragma unroll
        for (int i = 0; i < 8; i++)
#pragma unroll
            for (int j = 0; j < 8; j++)
                sMr[(r0 + i) * 132 + c0 + j] = acc[i][j] + b[c0 + j];
    }
    __syncthreads();

    // run-length pooled atomics (batch sorted -> few segments per block)
    if (tid < 128) {
        int j = tid;
        int gprev = sBat[0];
        float s = 0.f;
        for (int r = 0; r < 128; r++) {
            int g = sBat[r];
            if (g != gprev) {
                if (gprev >= 0) atomicAdd(&g_gsum[gprev * HID + j], s);
                s = 0.f;
                gprev = g;
            }
            if (g >= 0) s += sMr[r * 132 + j];
        }
        if (gprev >= 0) atomicAdd(&g_gsum[gprev * HID + j], s);
    }
}

// out = (gsum/gcnt) @ fc_w + fc_b     one graph per block
__global__ void k_final(const float* __restrict__ fcw,
                        const float* __restrict__ fcb,
                        float* __restrict__ out) {
    __shared__ float sg[HID];
    int g = blockIdx.x;
    if (threadIdx.x < HID) {
        float cnt = g_gcnt[g];
        if (cnt < 1.f) cnt = 1.f;
        sg[threadIdx.x] = g_gsum[g * HID + threadIdx.x] / cnt;
    }
    __syncthreads();
    int o = threadIdx.x;
    float a = fcb[o];
#pragma unroll 8
    for (int k = 0; k < HID; k++) a += sg[k] * fcw[k * OUT_DIM + o];
    out[g * OUT_DIM + o] = a;
}

// ---------------- host ----------------
extern "C" void kernel_launch(void* const* d_in, const int* in_sizes, int n_in,
                              void* d_out, int out_size) {
    const float* x        = (const float*)d_in[0];
    const int*   ei       = (const int*)d_in[1];
    const float* coord    = (const float*)d_in[2];
    const float* eattr    = (const float*)d_in[3];
    const int*   batch    = (const int*)d_in[4];
    const float* emb_in_w = (const float*)d_in[5];
    const float* emb_in_b = (const float*)d_in[6];
    const float* ew1      = (const float*)d_in[7];
    const float* eb1      = (const float*)d_in[8];
    const float* ew2      = (const float*)d_in[9];
    const float* eb2      = (const float*)d_in[10];
    const float* nw1      = (const float*)d_in[11];
    const float* nb1      = (const float*)d_in[12];
    const float* nw2      = (const float*)d_in[13];
    const float* nb2      = (const float*)d_in[14];
    const float* cw1      = (const float*)d_in[15];
    const float* cb1      = (const float*)d_in[16];
    const float* cw2      = (const float*)d_in[17];
    const float* eow      = (const float*)d_in[18];
    const float* eob      = (const float*)d_in[19];
    const float* fcw      = (const float*)d_in[20];
    const float* fcb      = (const float*)d_in[21];
    float* out = (float*)d_out;

    const int EDGE_SMEM = (32 * SMA + 32 * 128 + 128 * SMM + 256 + 128 + 128 + 384) * 4;
    const int NODE_SMEM = (32 * SMA + 32 * 128 + 128 * SMM) * 4;
    const int POOL_SMEM = (32 * SMA + 32 * 128 + 128 * 132 + 128) * 4;

    cudaFuncSetAttribute(k_edge, cudaFuncAttributeMaxDynamicSharedMemorySize, EDGE_SMEM);
    cudaFuncSetAttribute(k_node, cudaFuncAttributeMaxDynamicSharedMemorySize, NODE_SMEM);
    cudaFuncSetAttribute(k_pool, cudaFuncAttributeMaxDynamicSharedMemorySize, POOL_SMEM);

    const int EB = (N_EDGES + 127) / 128;   // 4688
    const int NB = (N_NODES + 127) / 128;   // 391

    k_init<<<(N_NODES * 3 + 255) / 256, 256>>>(coord);
    k_deg<<<(N_EDGES + 255) / 256, 256>>>(ei);
    k_gcnt<<<(N_NODES + 255) / 256, 256>>>(batch);
    k_emb_in<<<N_NODES, HID>>>(x, emb_in_w, emb_in_b);

    for (int l = 0; l < N_LAYERS; l++) {
        k_zero_acc<<<(N_NODES * HID / 4 + 255) / 256, 256>>>();
        k_edge<<<EB, 256, EDGE_SMEM>>>(
            ei, eattr,
            ew1 + l * 258 * HID, eb1 + l * HID,
            ew2 + l * HID * HID, eb2 + l * HID,
            cw1 + l * HID * HID, cb1 + l * HID,
            cw2 + l * HID);
        k_coord_apply<<<(N_NODES + 255) / 256, 256>>>();
        k_node<<<NB, 256, NODE_SMEM>>>(
            nw1 + l * 256 * HID, nb1 + l * HID,
            nw2 + l * HID * HID, nb2 + l * HID);
    }

    k_pool<<<NB, 256, POOL_SMEM>>>(batch, eow, eob);
    k_final<<<N_GRAPHS, OUT_DIM>>>(fcw, fcb, out);
}